// round 4
// baseline (speedup 1.0000x reference)
#include <cuda_runtime.h>
#include <cuda_bf16.h>
#include <math.h>
#include <stdint.h>

#define B_ 4096
#define M_ 4
#define D_ 512
#define N_ ((M_ + 1) * B_)   // 20480

// Static device scratch (no runtime allocation)
__device__ __nv_bfloat16 g_bf16[(size_t)N_ * D_];   // normalized rows, bf16, 20 MB
__device__ float g_denom[B_];
__device__ float g_loss_sum;

__device__ __forceinline__ float get_temp(int it) {
    if (it >= 300000) return 0.05f;
    float progress = (float)it / 300000.0f;
    return 0.05f + 0.5f * (0.2f - 0.05f) * (1.0f + cosf(3.14159265358979323846f * progress));
}

__device__ __forceinline__ uint32_t smem_u32(const void* p) {
    uint32_t a;
    asm("{ .reg .u64 t; cvta.to.shared.u64 t, %1; cvt.u32.u64 %0, t; }" : "=r"(a) : "l"(p));
    return a;
}

__device__ __forceinline__ uint32_t swz128(uint32_t off) {
    return off ^ ((off >> 3) & 0x70);
}

#define CP_ASYNC16(dst, src) \
    asm volatile("cp.async.cg.shared.global [%0], [%1], 16;" :: "r"(dst), "l"(src) : "memory")
#define CP_COMMIT() asm volatile("cp.async.commit_group;" ::: "memory")

#define LDMATRIX_X4(r0, r1, r2, r3, addr) \
    asm volatile("ldmatrix.sync.aligned.m8n8.x4.shared.b16 {%0,%1,%2,%3}, [%4];" \
                 : "=r"(r0), "=r"(r1), "=r"(r2), "=r"(r3) : "r"(addr))

#define MMA_BF16(d, a, b0, b1) \
    asm volatile("mma.sync.aligned.m16n8k16.row.col.f32.bf16.bf16.f32 " \
                 "{%0,%1,%2,%3}, {%4,%5,%6,%7}, {%8,%9}, {%0,%1,%2,%3};" \
                 : "+f"((d)[0]), "+f"((d)[1]), "+f"((d)[2]), "+f"((d)[3]) \
                 : "r"((a)[0]), "r"((a)[1]), "r"((a)[2]), "r"((a)[3]), \
                   "r"(b0), "r"(b1))

// ---------------------------------------------------------------------------
// Kernel 1: L2-normalize every row into g_bf16; zero accumulators.
// ---------------------------------------------------------------------------
__global__ void normalize_kernel(const float* __restrict__ orig,
                                 const float* __restrict__ masked) {
    int row = blockIdx.x;
    const float* src = (row < B_) ? (orig + (size_t)row * D_)
                                  : (masked + (size_t)(row - B_) * D_);
    int t = threadIdx.x;  // 0..127
    float4 v = ((const float4*)src)[t];
    float s = v.x * v.x + v.y * v.y + v.z * v.z + v.w * v.w;
    #pragma unroll
    for (int off = 16; off > 0; off >>= 1)
        s += __shfl_down_sync(0xffffffffu, s, off);
    __shared__ float sm[4];
    __shared__ float s_inv;
    if ((t & 31) == 0) sm[t >> 5] = s;
    __syncthreads();
    if (t == 0) {
        float tot = sm[0] + sm[1] + sm[2] + sm[3];
        s_inv = 1.0f / fmaxf(sqrtf(tot), 1e-12f);
        if (row < B_) g_denom[row] = 0.0f;
        if (row == 0) g_loss_sum = 0.0f;
    }
    __syncthreads();
    float inv = s_inv;
    __nv_bfloat162 lo = __floats2bfloat162_rn(v.x * inv, v.y * inv);
    __nv_bfloat162 hi = __floats2bfloat162_rn(v.z * inv, v.w * inv);
    __nv_bfloat162* dst = (__nv_bfloat162*)(g_bf16 + (size_t)row * D_);
    dst[2 * t]     = lo;
    dst[2 * t + 1] = hi;
}

// ---------------------------------------------------------------------------
// Kernel 2: HMMA exp-GEMM. Tile 128x128, 4 warps (warp = 64x64), 128 threads.
// K=512 in 8 chunks of 64; 3-stage cp.async pipeline; SW128 swizzle.
// 2 CTAs/SM: co-resident CTA hides epilogue/sync bubbles.
// ---------------------------------------------------------------------------
#define TILE 128
#define NCHUNK 8
#define NSTAGE 3
#define STG_A_SZ (TILE * 128)   // 16 KB
#define STG_B_SZ (TILE * 128)   // 16 KB
#define SMEM_A_OFF 1024
#define SMEM_B_OFF (SMEM_A_OFF + NSTAGE * STG_A_SZ)
#define SMEM_TOTAL (SMEM_B_OFF + NSTAGE * STG_B_SZ)   // 99328 B

__device__ __forceinline__ void load_chunk(int chunk, int stage, uint32_t sb,
                                           const char* gA, const char* gB, int tid) {
    // 128 threads; thread tid owns row tid of both tiles: 8 x 16B each.
    const char* asrc = gA + (size_t)tid * 1024 + chunk * 128;
    const char* bsrc = gB + (size_t)tid * 1024 + chunk * 128;
    const uint32_t abase = sb + SMEM_A_OFF + stage * STG_A_SZ;
    const uint32_t bbase = sb + SMEM_B_OFF + stage * STG_B_SZ;
    #pragma unroll
    for (int c = 0; c < 8; c++) {
        uint32_t off = (uint32_t)tid * 128 + c * 16;
        CP_ASYNC16(abase + swz128(off), asrc + c * 16);
        CP_ASYNC16(bbase + swz128(off), bsrc + c * 16);
    }
}

__global__ __launch_bounds__(128, 2) void gemm_hmma_kernel(const int* __restrict__ d_iter) {
    extern __shared__ __align__(1024) char smem[];
    float* sdenom = (float*)smem;   // 128 floats at offset 0
    uint32_t sb = smem_u32(smem);

    const int tid  = threadIdx.x;
    const int wid  = tid >> 5;
    const int lane = tid & 31;
    const int warpM = wid & 1;        // 0/1 -> rows 0-63 / 64-127
    const int warpN = wid >> 1;       // 0/1 -> cols 0-63 / 64-127
    const int rowBase = blockIdx.y * TILE;
    const int colBase = blockIdx.x * TILE;
    const char* gA = (const char*)(g_bf16 + (size_t)rowBase * D_);
    const char* gB = (const char*)(g_bf16 + (size_t)colBase * D_);

    sdenom[tid] = 0.0f;

    load_chunk(0, 0, sb, gA, gB, tid); CP_COMMIT();
    load_chunk(1, 1, sb, gA, gB, tid); CP_COMMIT();

    float acc[4][8][4];
    #pragma unroll
    for (int mt = 0; mt < 4; mt++)
        #pragma unroll
        for (int nt = 0; nt < 8; nt++)
            #pragma unroll
            for (int f = 0; f < 4; f++) acc[mt][nt][f] = 0.0f;

    // per-lane fragment address components
    const int a_row = warpM * 64 + (lane & 15);                       // + mt*16
    const int a_kb  = (lane >> 4) * 16;                               // + kk*32
    const int b_row = warpN * 64 + ((lane >> 4) << 3) + (lane & 7);   // + ntp*16
    const int b_kb  = ((lane >> 3) & 1) * 16;                         // + kk*32

    #pragma unroll
    for (int k = 0; k < NCHUNK; k++) {
        if (k < NCHUNK - 1) asm volatile("cp.async.wait_group 1;" ::: "memory");
        else                asm volatile("cp.async.wait_group 0;" ::: "memory");
        __syncthreads();
        if (k + 2 < NCHUNK) {
            load_chunk(k + 2, (k + 2) % NSTAGE, sb, gA, gB, tid);
            CP_COMMIT();
        }

        const int st = k % NSTAGE;
        const uint32_t Ab = sb + SMEM_A_OFF + st * STG_A_SZ;
        const uint32_t Bb = sb + SMEM_B_OFF + st * STG_B_SZ;

        #pragma unroll
        for (int kk = 0; kk < 4; kk++) {
            uint32_t a[4][4];
            #pragma unroll
            for (int mt = 0; mt < 4; mt++) {
                uint32_t off = (uint32_t)(a_row + mt * 16) * 128 + kk * 32 + a_kb;
                LDMATRIX_X4(a[mt][0], a[mt][1], a[mt][2], a[mt][3], Ab + swz128(off));
            }
            uint32_t b[4][4];
            #pragma unroll
            for (int ntp = 0; ntp < 4; ntp++) {
                uint32_t off = (uint32_t)(b_row + ntp * 16) * 128 + kk * 32 + b_kb;
                LDMATRIX_X4(b[ntp][0], b[ntp][1], b[ntp][2], b[ntp][3], Bb + swz128(off));
            }
            #pragma unroll
            for (int mt = 0; mt < 4; mt++)
                #pragma unroll
                for (int nt = 0; nt < 8; nt++)
                    MMA_BF16(acc[mt][nt], a[mt], b[nt >> 1][(nt & 1) * 2],
                             b[nt >> 1][(nt & 1) * 2 + 1]);
        }
    }

    // Epilogue: exp, diag mask, row sums
    const float invT = 1.0f / get_temp(d_iter[0]);
    #pragma unroll
    for (int mt = 0; mt < 4; mt++) {
        const int r0 = warpM * 64 + mt * 16 + (lane >> 2);  // local row
        const int gi0 = rowBase + r0;
        const int gi1 = gi0 + 8;
        float rs0 = 0.0f, rs1 = 0.0f;
        #pragma unroll
        for (int nt = 0; nt < 8; nt++) {
            const int col = colBase + warpN * 64 + nt * 8 + 2 * (lane & 3);
            float e0 = __expf(acc[mt][nt][0] * invT);
            float e1 = __expf(acc[mt][nt][1] * invT);
            float e2 = __expf(acc[mt][nt][2] * invT);
            float e3 = __expf(acc[mt][nt][3] * invT);
            if (col != gi0)     rs0 += e0;
            if (col + 1 != gi0) rs0 += e1;
            if (col != gi1)     rs1 += e2;
            if (col + 1 != gi1) rs1 += e3;
        }
        rs0 += __shfl_xor_sync(0xffffffffu, rs0, 1);
        rs0 += __shfl_xor_sync(0xffffffffu, rs0, 2);
        rs1 += __shfl_xor_sync(0xffffffffu, rs1, 1);
        rs1 += __shfl_xor_sync(0xffffffffu, rs1, 2);
        if ((lane & 3) == 0) {
            atomicAdd(&sdenom[r0], rs0);
            atomicAdd(&sdenom[r0 + 8], rs1);
        }
    }
    __syncthreads();
    atomicAdd(&g_denom[rowBase + tid], sdenom[tid]);
}

// ---------------------------------------------------------------------------
// Kernel 3: positives + per-row loss (bf16 inputs, fp32 dots).
// ---------------------------------------------------------------------------
__global__ void pos_loss_kernel(const int* __restrict__ d_iter) {
    const int i = blockIdx.x;
    const int t = threadIdx.x;  // 0..127, 4 bf16 elems each
    const __nv_bfloat162* q = (const __nv_bfloat162*)(g_bf16 + (size_t)i * D_);
    __nv_bfloat162 q0 = q[2 * t], q1 = q[2 * t + 1];
    float2 qa = __bfloat1622float2(q0), qb = __bfloat1622float2(q1);
    float p[M_];
    #pragma unroll
    for (int m = 0; m < M_; m++) {
        const __nv_bfloat162* kv =
            (const __nv_bfloat162*)(g_bf16 + (size_t)((m + 1) * B_ + i) * D_);
        float2 ka = __bfloat1622float2(kv[2 * t]);
        float2 kb = __bfloat1622float2(kv[2 * t + 1]);
        p[m] = qa.x * ka.x + qa.y * ka.y + qb.x * kb.x + qb.y * kb.y;
    }
    __shared__ float sm[M_][4];
    #pragma unroll
    for (int m = 0; m < M_; m++) {
        float v = p[m];
        #pragma unroll
        for (int off = 16; off > 0; off >>= 1)
            v += __shfl_down_sync(0xffffffffu, v, off);
        if ((t & 31) == 0) sm[m][t >> 5] = v;
    }
    __syncthreads();
    if (t == 0) {
        const float invT = 1.0f / get_temp(d_iter[0]);
        float pos = 0.0f;
        #pragma unroll
        for (int m = 0; m < M_; m++) {
            float d = sm[m][0] + sm[m][1] + sm[m][2] + sm[m][3];
            pos += __expf(d * invT);
        }
        const float denom = g_denom[i];
        const float loss = logf(denom + 1e-8f) - logf(pos);
        atomicAdd(&g_loss_sum, loss);
    }
}

__global__ void finalize_kernel(float* __restrict__ out) {
    out[0] = g_loss_sum * (1.0f / (float)B_);
}

// ---------------------------------------------------------------------------
extern "C" void kernel_launch(void* const* d_in, const int* in_sizes, int n_in,
                              void* d_out, int out_size) {
    const float* orig   = (const float*)d_in[0];
    const float* masked = (const float*)d_in[1];
    const int*   iter   = (const int*)d_in[2];
    float* out = (float*)d_out;

    cudaFuncSetAttribute(gemm_hmma_kernel,
                         cudaFuncAttributeMaxDynamicSharedMemorySize, SMEM_TOTAL);

    normalize_kernel<<<N_, 128>>>(orig, masked);
    gemm_hmma_kernel<<<dim3(N_ / TILE, B_ / TILE), 128, SMEM_TOTAL>>>(iter);
    pos_loss_kernel<<<B_, 128>>>(iter);
    finalize_kernel<<<1, 1>>>(out);
}

// round 5
// speedup vs baseline: 1.2141x; 1.2141x over previous
#include <cuda_runtime.h>
#include <cuda_bf16.h>
#include <math.h>
#include <stdint.h>

#define B_ 4096
#define M_ 4
#define D_ 512
#define N_ ((M_ + 1) * B_)   // 20480

// Static device scratch (no runtime allocation)
__device__ __nv_bfloat16 g_bf16[(size_t)N_ * D_];   // normalized rows, bf16, 20 MB
__device__ float g_denom[B_];
__device__ float g_loss_sum;

__device__ __forceinline__ float get_temp(int it) {
    if (it >= 300000) return 0.05f;
    float progress = (float)it / 300000.0f;
    return 0.05f + 0.5f * (0.2f - 0.05f) * (1.0f + cosf(3.14159265358979323846f * progress));
}

__device__ __forceinline__ uint32_t smem_u32(const void* p) {
    uint32_t a;
    asm("{ .reg .u64 t; cvta.to.shared.u64 t, %1; cvt.u32.u64 %0, t; }" : "=r"(a) : "l"(p));
    return a;
}

__device__ __forceinline__ uint32_t swz128(uint32_t off) {
    return off ^ ((off >> 3) & 0x70);
}

#define CP_ASYNC16(dst, src) \
    asm volatile("cp.async.cg.shared.global [%0], [%1], 16;" :: "r"(dst), "l"(src) : "memory")
#define CP_COMMIT() asm volatile("cp.async.commit_group;" ::: "memory")

#define LDMATRIX_X4(r0, r1, r2, r3, addr) \
    asm volatile("ldmatrix.sync.aligned.m8n8.x4.shared.b16 {%0,%1,%2,%3}, [%4];" \
                 : "=r"(r0), "=r"(r1), "=r"(r2), "=r"(r3) : "r"(addr))

#define MMA_BF16(d, a, b0, b1) \
    asm volatile("mma.sync.aligned.m16n8k16.row.col.f32.bf16.bf16.f32 " \
                 "{%0,%1,%2,%3}, {%4,%5,%6,%7}, {%8,%9}, {%0,%1,%2,%3};" \
                 : "+f"((d)[0]), "+f"((d)[1]), "+f"((d)[2]), "+f"((d)[3]) \
                 : "r"((a)[0]), "r"((a)[1]), "r"((a)[2]), "r"((a)[3]), \
                   "r"(b0), "r"(b1))

// ---------------------------------------------------------------------------
// Kernel 1: L2-normalize every row into g_bf16; zero accumulators.
// ---------------------------------------------------------------------------
__global__ void normalize_kernel(const float* __restrict__ orig,
                                 const float* __restrict__ masked) {
    int row = blockIdx.x;
    const float* src = (row < B_) ? (orig + (size_t)row * D_)
                                  : (masked + (size_t)(row - B_) * D_);
    int t = threadIdx.x;  // 0..127
    float4 v = ((const float4*)src)[t];
    float s = v.x * v.x + v.y * v.y + v.z * v.z + v.w * v.w;
    #pragma unroll
    for (int off = 16; off > 0; off >>= 1)
        s += __shfl_down_sync(0xffffffffu, s, off);
    __shared__ float sm[4];
    __shared__ float s_inv;
    if ((t & 31) == 0) sm[t >> 5] = s;
    __syncthreads();
    if (t == 0) {
        float tot = sm[0] + sm[1] + sm[2] + sm[3];
        s_inv = 1.0f / fmaxf(sqrtf(tot), 1e-12f);
        if (row < B_) g_denom[row] = 0.0f;
        if (row == 0) g_loss_sum = 0.0f;
    }
    __syncthreads();
    float inv = s_inv;
    __nv_bfloat162 lo = __floats2bfloat162_rn(v.x * inv, v.y * inv);
    __nv_bfloat162 hi = __floats2bfloat162_rn(v.z * inv, v.w * inv);
    __nv_bfloat162* dst = (__nv_bfloat162*)(g_bf16 + (size_t)row * D_);
    dst[2 * t]     = lo;
    dst[2 * t + 1] = hi;
}

// ---------------------------------------------------------------------------
// Kernel 2: HMMA exp-GEMM. CTA tile 128(M) x 256(N), 512 threads, 16 warps,
// warp tile 32x64 (4 warps per SMSP for latency hiding).
// K=512 in 8 chunks of 64; 3-stage cp.async pipeline; SW128 swizzle.
// ---------------------------------------------------------------------------
#define TILE_M 128
#define TILE_N 256
#define NCHUNK 8
#define NSTAGE 3
#define STG_A_SZ (TILE_M * 128)   // 16 KB
#define STG_B_SZ (TILE_N * 128)   // 32 KB
#define SMEM_A_OFF 1024
#define SMEM_B_OFF (SMEM_A_OFF + NSTAGE * STG_A_SZ)
#define SMEM_TOTAL (SMEM_B_OFF + NSTAGE * STG_B_SZ)   // 148480 B

__device__ __forceinline__ void load_chunk(int chunk, int stage, uint32_t sb,
                                           const char* gA, const char* gB, int tid) {
    // A: 128 rows x 8 segs = 1024 segs; thread -> row tid&127, segs 2*(tid>>7)+{0,1}
    {
        const int row = tid & 127;
        const int c0 = (tid >> 7) * 2;
        const char* asrc = gA + (size_t)row * 1024 + chunk * 128 + c0 * 16;
        const uint32_t abase = sb + SMEM_A_OFF + stage * STG_A_SZ;
        #pragma unroll
        for (int c = 0; c < 2; c++) {
            uint32_t off = (uint32_t)row * 128 + (c0 + c) * 16;
            CP_ASYNC16(abase + swz128(off), asrc + c * 16);
        }
    }
    // B: 256 rows x 8 segs = 2048 segs; thread -> row tid>>1, segs 4*(tid&1)+{0..3}
    {
        const int row = tid >> 1;
        const int c0 = (tid & 1) * 4;
        const char* bsrc = gB + (size_t)row * 1024 + chunk * 128 + c0 * 16;
        const uint32_t bbase = sb + SMEM_B_OFF + stage * STG_B_SZ;
        #pragma unroll
        for (int c = 0; c < 4; c++) {
            uint32_t off = (uint32_t)row * 128 + (c0 + c) * 16;
            CP_ASYNC16(bbase + swz128(off), bsrc + c * 16);
        }
    }
}

__global__ __launch_bounds__(512, 1) void gemm_hmma_kernel(const int* __restrict__ d_iter) {
    extern __shared__ __align__(1024) char smem[];
    float* sdenom = (float*)smem;   // 128 floats at offset 0
    uint32_t sb = smem_u32(smem);

    const int tid  = threadIdx.x;
    const int wid  = tid >> 5;
    const int lane = tid & 31;
    const int warpM = wid & 3;        // 0..3 -> 32 rows each
    const int warpN = wid >> 2;       // 0..3 -> 64 cols each
    const int rowBase = blockIdx.y * TILE_M;
    const int colBase = blockIdx.x * TILE_N;
    const char* gA = (const char*)(g_bf16 + (size_t)rowBase * D_);
    const char* gB = (const char*)(g_bf16 + (size_t)colBase * D_);

    if (tid < TILE_M) sdenom[tid] = 0.0f;

    load_chunk(0, 0, sb, gA, gB, tid); CP_COMMIT();
    load_chunk(1, 1, sb, gA, gB, tid); CP_COMMIT();

    float acc[2][8][4];
    #pragma unroll
    for (int mt = 0; mt < 2; mt++)
        #pragma unroll
        for (int nt = 0; nt < 8; nt++)
            #pragma unroll
            for (int f = 0; f < 4; f++) acc[mt][nt][f] = 0.0f;

    // per-lane fragment address components
    const int a_row = warpM * 32 + (lane & 15);                       // + mt*16
    const int a_kb  = (lane >> 4) * 16;                               // + kk*32
    const int b_row = warpN * 64 + ((lane >> 4) << 3) + (lane & 7);   // + ntp*16
    const int b_kb  = ((lane >> 3) & 1) * 16;                         // + kk*32

    #pragma unroll
    for (int k = 0; k < NCHUNK; k++) {
        if (k < NCHUNK - 1) asm volatile("cp.async.wait_group 1;" ::: "memory");
        else                asm volatile("cp.async.wait_group 0;" ::: "memory");
        __syncthreads();
        if (k + 2 < NCHUNK) {
            load_chunk(k + 2, (k + 2) % NSTAGE, sb, gA, gB, tid);
            CP_COMMIT();
        }

        const int st = k % NSTAGE;
        const uint32_t Ab = sb + SMEM_A_OFF + st * STG_A_SZ;
        const uint32_t Bb = sb + SMEM_B_OFF + st * STG_B_SZ;

        #pragma unroll
        for (int kk = 0; kk < 4; kk++) {
            uint32_t a[2][4];
            #pragma unroll
            for (int mt = 0; mt < 2; mt++) {
                uint32_t off = (uint32_t)(a_row + mt * 16) * 128 + kk * 32 + a_kb;
                LDMATRIX_X4(a[mt][0], a[mt][1], a[mt][2], a[mt][3], Ab + swz128(off));
            }
            uint32_t b[4][4];
            #pragma unroll
            for (int ntp = 0; ntp < 4; ntp++) {
                uint32_t off = (uint32_t)(b_row + ntp * 16) * 128 + kk * 32 + b_kb;
                LDMATRIX_X4(b[ntp][0], b[ntp][1], b[ntp][2], b[ntp][3], Bb + swz128(off));
            }
            #pragma unroll
            for (int mt = 0; mt < 2; mt++)
                #pragma unroll
                for (int nt = 0; nt < 8; nt++)
                    MMA_BF16(acc[mt][nt], a[mt], b[nt >> 1][(nt & 1) * 2],
                             b[nt >> 1][(nt & 1) * 2 + 1]);
        }
    }

    // Epilogue: exp, diag mask, row sums
    const float invT = 1.0f / get_temp(d_iter[0]);
    #pragma unroll
    for (int mt = 0; mt < 2; mt++) {
        const int r0 = warpM * 32 + mt * 16 + (lane >> 2);  // local row
        const int gi0 = rowBase + r0;
        const int gi1 = gi0 + 8;
        float rs0 = 0.0f, rs1 = 0.0f;
        #pragma unroll
        for (int nt = 0; nt < 8; nt++) {
            const int col = colBase + warpN * 64 + nt * 8 + 2 * (lane & 3);
            float e0 = __expf(acc[mt][nt][0] * invT);
            float e1 = __expf(acc[mt][nt][1] * invT);
            float e2 = __expf(acc[mt][nt][2] * invT);
            float e3 = __expf(acc[mt][nt][3] * invT);
            if (col != gi0)     rs0 += e0;
            if (col + 1 != gi0) rs0 += e1;
            if (col != gi1)     rs1 += e2;
            if (col + 1 != gi1) rs1 += e3;
        }
        rs0 += __shfl_xor_sync(0xffffffffu, rs0, 1);
        rs0 += __shfl_xor_sync(0xffffffffu, rs0, 2);
        rs1 += __shfl_xor_sync(0xffffffffu, rs1, 1);
        rs1 += __shfl_xor_sync(0xffffffffu, rs1, 2);
        if ((lane & 3) == 0) {
            atomicAdd(&sdenom[r0], rs0);
            atomicAdd(&sdenom[r0 + 8], rs1);
        }
    }
    __syncthreads();
    if (tid < TILE_M) atomicAdd(&g_denom[rowBase + tid], sdenom[tid]);
}

// ---------------------------------------------------------------------------
// Kernel 3: positives + per-row loss (bf16 inputs, fp32 dots).
// ---------------------------------------------------------------------------
__global__ void pos_loss_kernel(const int* __restrict__ d_iter) {
    const int i = blockIdx.x;
    const int t = threadIdx.x;  // 0..127, 4 bf16 elems each
    const __nv_bfloat162* q = (const __nv_bfloat162*)(g_bf16 + (size_t)i * D_);
    __nv_bfloat162 q0 = q[2 * t], q1 = q[2 * t + 1];
    float2 qa = __bfloat1622float2(q0), qb = __bfloat1622float2(q1);
    float p[M_];
    #pragma unroll
    for (int m = 0; m < M_; m++) {
        const __nv_bfloat162* kv =
            (const __nv_bfloat162*)(g_bf16 + (size_t)((m + 1) * B_ + i) * D_);
        float2 ka = __bfloat1622float2(kv[2 * t]);
        float2 kb = __bfloat1622float2(kv[2 * t + 1]);
        p[m] = qa.x * ka.x + qa.y * ka.y + qb.x * kb.x + qb.y * kb.y;
    }
    __shared__ float sm[M_][4];
    #pragma unroll
    for (int m = 0; m < M_; m++) {
        float v = p[m];
        #pragma unroll
        for (int off = 16; off > 0; off >>= 1)
            v += __shfl_down_sync(0xffffffffu, v, off);
        if ((t & 31) == 0) sm[m][t >> 5] = v;
    }
    __syncthreads();
    if (t == 0) {
        const float invT = 1.0f / get_temp(d_iter[0]);
        float pos = 0.0f;
        #pragma unroll
        for (int m = 0; m < M_; m++) {
            float d = sm[m][0] + sm[m][1] + sm[m][2] + sm[m][3];
            pos += __expf(d * invT);
        }
        const float denom = g_denom[i];
        const float loss = logf(denom + 1e-8f) - logf(pos);
        atomicAdd(&g_loss_sum, loss);
    }
}

__global__ void finalize_kernel(float* __restrict__ out) {
    out[0] = g_loss_sum * (1.0f / (float)B_);
}

// ---------------------------------------------------------------------------
extern "C" void kernel_launch(void* const* d_in, const int* in_sizes, int n_in,
                              void* d_out, int out_size) {
    const float* orig   = (const float*)d_in[0];
    const float* masked = (const float*)d_in[1];
    const int*   iter   = (const int*)d_in[2];
    float* out = (float*)d_out;

    cudaFuncSetAttribute(gemm_hmma_kernel,
                         cudaFuncAttributeMaxDynamicSharedMemorySize, SMEM_TOTAL);

    normalize_kernel<<<N_, 128>>>(orig, masked);
    gemm_hmma_kernel<<<dim3(N_ / TILE_N, B_ / TILE_M), 512, SMEM_TOTAL>>>(iter);
    pos_loss_kernel<<<B_, 128>>>(iter);
    finalize_kernel<<<1, 1>>>(out);
}

// round 6
// speedup vs baseline: 1.2229x; 1.0073x over previous
#include <cuda_runtime.h>
#include <cuda_bf16.h>
#include <math.h>
#include <stdint.h>

#define B_ 4096
#define M_ 4
#define D_ 512
#define N_ ((M_ + 1) * B_)   // 20480

// Static device scratch (no runtime allocation)
__device__ uint8_t g_fp8[(size_t)N_ * D_];   // normalized rows * 16, e4m3, 10 MB
__device__ float g_denom[B_];
__device__ float g_loss_sum;

__device__ __forceinline__ float get_temp(int it) {
    if (it >= 300000) return 0.05f;
    float progress = (float)it / 300000.0f;
    return 0.05f + 0.5f * (0.2f - 0.05f) * (1.0f + cosf(3.14159265358979323846f * progress));
}

__device__ __forceinline__ uint32_t smem_u32(const void* p) {
    uint32_t a;
    asm("{ .reg .u64 t; cvta.to.shared.u64 t, %1; cvt.u32.u64 %0, t; }" : "=r"(a) : "l"(p));
    return a;
}

__device__ __forceinline__ uint32_t swz128(uint32_t off) {
    return off ^ ((off >> 3) & 0x70);
}

#define CP_ASYNC16(dst, src) \
    asm volatile("cp.async.cg.shared.global [%0], [%1], 16;" :: "r"(dst), "l"(src) : "memory")
#define CP_COMMIT() asm volatile("cp.async.commit_group;" ::: "memory")

#define LDMATRIX_X4(r0, r1, r2, r3, addr) \
    asm volatile("ldmatrix.sync.aligned.m8n8.x4.shared.b16 {%0,%1,%2,%3}, [%4];" \
                 : "=r"(r0), "=r"(r1), "=r"(r2), "=r"(r3) : "r"(addr))

#define MMA_FP8(d, a, b0, b1) \
    asm volatile("mma.sync.aligned.m16n8k32.row.col.f32.e4m3.e4m3.f32 " \
                 "{%0,%1,%2,%3}, {%4,%5,%6,%7}, {%8,%9}, {%0,%1,%2,%3};" \
                 : "+f"((d)[0]), "+f"((d)[1]), "+f"((d)[2]), "+f"((d)[3]) \
                 : "r"((a)[0]), "r"((a)[1]), "r"((a)[2]), "r"((a)[3]), \
                   "r"(b0), "r"(b1))

// pack 2 floats to e4m3x2 (first src -> high byte)
__device__ __forceinline__ uint16_t pack_e4m3x2(float lo, float hi) {
    uint16_t r;
    asm("cvt.rn.satfinite.e4m3x2.f32 %0, %1, %2;" : "=h"(r) : "f"(hi), "f"(lo));
    return r;
}

// ---------------------------------------------------------------------------
// Kernel 1: L2-normalize every row, scale by 16, quantize to e4m3 in g_fp8.
// Also zeroes accumulators.
// ---------------------------------------------------------------------------
__global__ void normalize_kernel(const float* __restrict__ orig,
                                 const float* __restrict__ masked) {
    int row = blockIdx.x;
    const float* src = (row < B_) ? (orig + (size_t)row * D_)
                                  : (masked + (size_t)(row - B_) * D_);
    int t = threadIdx.x;  // 0..127
    float4 v = ((const float4*)src)[t];
    float s = v.x * v.x + v.y * v.y + v.z * v.z + v.w * v.w;
    #pragma unroll
    for (int off = 16; off > 0; off >>= 1)
        s += __shfl_down_sync(0xffffffffu, s, off);
    __shared__ float sm[4];
    __shared__ float s_inv;
    if ((t & 31) == 0) sm[t >> 5] = s;
    __syncthreads();
    if (t == 0) {
        float tot = sm[0] + sm[1] + sm[2] + sm[3];
        s_inv = 16.0f / fmaxf(sqrtf(tot), 1e-12f);   // x16 scale for e4m3 range
        if (row < B_) g_denom[row] = 0.0f;
        if (row == 0) g_loss_sum = 0.0f;
    }
    __syncthreads();
    float inv = s_inv;
    uint16_t lo = pack_e4m3x2(v.x * inv, v.y * inv);
    uint16_t hi = pack_e4m3x2(v.z * inv, v.w * inv);
    ((uint32_t*)(g_fp8 + (size_t)row * D_))[t] = (uint32_t)lo | ((uint32_t)hi << 16);
}

// ---------------------------------------------------------------------------
// Kernel 2: FP8 HMMA exp-GEMM. CTA tile 128x128, 8 warps (warp = 64x32),
// 256 threads, 2 CTAs/SM (R3's winning shape).
// K=512 fp8 in 4 chunks of 128 (128 B rows); 3-stage cp.async; SW128 swizzle.
// acc = 256 * sim (due to x16 quantization scale).
// ---------------------------------------------------------------------------
#define TILE 128
#define NCHUNK 4
#define NSTAGE 3
#define STG_A_SZ (TILE * 128)   // 16 KB
#define STG_B_SZ (TILE * 128)   // 16 KB
#define SMEM_A_OFF 1024
#define SMEM_B_OFF (SMEM_A_OFF + NSTAGE * STG_A_SZ)
#define SMEM_TOTAL (SMEM_B_OFF + NSTAGE * STG_B_SZ)   // 99328 B

__device__ __forceinline__ void load_chunk(int chunk, int stage, uint32_t sb,
                                           const char* gA, const char* gB, int tid) {
    // 256 threads; each loads 4 x 16B of A and 4 x 16B of B.
    const int row = tid >> 1;
    const int c0 = (tid & 1) * 4;
    const char* asrc = gA + (size_t)row * D_ + chunk * 128 + c0 * 16;
    const char* bsrc = gB + (size_t)row * D_ + chunk * 128 + c0 * 16;
    const uint32_t abase = sb + SMEM_A_OFF + stage * STG_A_SZ;
    const uint32_t bbase = sb + SMEM_B_OFF + stage * STG_B_SZ;
    #pragma unroll
    for (int c = 0; c < 4; c++) {
        uint32_t off = (uint32_t)row * 128 + (c0 + c) * 16;
        CP_ASYNC16(abase + swz128(off), asrc + c * 16);
        CP_ASYNC16(bbase + swz128(off), bsrc + c * 16);
    }
}

__global__ __launch_bounds__(256, 2) void gemm_fp8_kernel(const int* __restrict__ d_iter) {
    extern __shared__ __align__(1024) char smem[];
    float* sdenom = (float*)smem;   // 128 floats at offset 0
    uint32_t sb = smem_u32(smem);

    const int tid  = threadIdx.x;
    const int wid  = tid >> 5;
    const int lane = tid & 31;
    const int warpM = wid & 1;        // 0/1 -> 64 rows each
    const int warpN = wid >> 1;       // 0..3 -> 32 cols each
    const int rowBase = blockIdx.y * TILE;
    const int colBase = blockIdx.x * TILE;
    const char* gA = (const char*)(g_fp8 + (size_t)rowBase * D_);
    const char* gB = (const char*)(g_fp8 + (size_t)colBase * D_);

    if (tid < TILE) sdenom[tid] = 0.0f;

    load_chunk(0, 0, sb, gA, gB, tid); CP_COMMIT();
    load_chunk(1, 1, sb, gA, gB, tid); CP_COMMIT();

    float acc[4][4][4];
    #pragma unroll
    for (int mt = 0; mt < 4; mt++)
        #pragma unroll
        for (int nt = 0; nt < 4; nt++)
            #pragma unroll
            for (int f = 0; f < 4; f++) acc[mt][nt][f] = 0.0f;

    // per-lane fragment address components (byte offsets within 128B rows)
    // A x4: m0 rows0-7/kb0, m1 rows8-15/kb0, m2 rows0-7/kb16, m3 rows8-15/kb16
    const int a_row = warpM * 64 + (lane & 15);                       // + mt*16
    const int a_kb  = (lane >> 4) * 16;                               // + kk*32
    // B x4: m0 n0-7/kb0, m1 n0-7/kb16, m2 n8-15/kb0, m3 n8-15/kb16
    const int b_row = warpN * 32 + ((lane >> 4) << 3) + (lane & 7);   // + ntp*16
    const int b_kb  = ((lane >> 3) & 1) * 16;                         // + kk*32

    #pragma unroll
    for (int k = 0; k < NCHUNK; k++) {
        if (k < NCHUNK - 1) asm volatile("cp.async.wait_group 1;" ::: "memory");
        else                asm volatile("cp.async.wait_group 0;" ::: "memory");
        __syncthreads();
        if (k + 2 < NCHUNK) {
            load_chunk(k + 2, (k + 2) % NSTAGE, sb, gA, gB, tid);
            CP_COMMIT();
        }

        const int st = k % NSTAGE;
        const uint32_t Ab = sb + SMEM_A_OFF + st * STG_A_SZ;
        const uint32_t Bb = sb + SMEM_B_OFF + st * STG_B_SZ;

        #pragma unroll
        for (int kk = 0; kk < 4; kk++) {   // 4 x K=32 fp8 steps per 128-chunk
            uint32_t a[4][4];
            #pragma unroll
            for (int mt = 0; mt < 4; mt++) {
                uint32_t off = (uint32_t)(a_row + mt * 16) * 128 + kk * 32 + a_kb;
                LDMATRIX_X4(a[mt][0], a[mt][1], a[mt][2], a[mt][3], Ab + swz128(off));
            }
            uint32_t b[2][4];
            #pragma unroll
            for (int ntp = 0; ntp < 2; ntp++) {
                uint32_t off = (uint32_t)(b_row + ntp * 16) * 128 + kk * 32 + b_kb;
                LDMATRIX_X4(b[ntp][0], b[ntp][1], b[ntp][2], b[ntp][3], Bb + swz128(off));
            }
            #pragma unroll
            for (int mt = 0; mt < 4; mt++)
                #pragma unroll
                for (int nt = 0; nt < 4; nt++)
                    MMA_FP8(acc[mt][nt], a[mt], b[nt >> 1][(nt & 1) * 2],
                            b[nt >> 1][(nt & 1) * 2 + 1]);
        }
    }

    // Epilogue: exp, diag mask, row sums. acc = 256*sim -> scale = invT/256.
    const float scale = (1.0f / get_temp(d_iter[0])) * (1.0f / 256.0f);
    #pragma unroll
    for (int mt = 0; mt < 4; mt++) {
        const int r0 = warpM * 64 + mt * 16 + (lane >> 2);  // local row
        const int gi0 = rowBase + r0;
        const int gi1 = gi0 + 8;
        float rs0 = 0.0f, rs1 = 0.0f;
        #pragma unroll
        for (int nt = 0; nt < 4; nt++) {
            const int col = colBase + warpN * 32 + nt * 8 + 2 * (lane & 3);
            float e0 = __expf(acc[mt][nt][0] * scale);
            float e1 = __expf(acc[mt][nt][1] * scale);
            float e2 = __expf(acc[mt][nt][2] * scale);
            float e3 = __expf(acc[mt][nt][3] * scale);
            if (col != gi0)     rs0 += e0;
            if (col + 1 != gi0) rs0 += e1;
            if (col != gi1)     rs1 += e2;
            if (col + 1 != gi1) rs1 += e3;
        }
        rs0 += __shfl_xor_sync(0xffffffffu, rs0, 1);
        rs0 += __shfl_xor_sync(0xffffffffu, rs0, 2);
        rs1 += __shfl_xor_sync(0xffffffffu, rs1, 1);
        rs1 += __shfl_xor_sync(0xffffffffu, rs1, 2);
        if ((lane & 3) == 0) {
            atomicAdd(&sdenom[r0], rs0);
            atomicAdd(&sdenom[r0 + 8], rs1);
        }
    }
    __syncthreads();
    if (tid < TILE) atomicAdd(&g_denom[rowBase + tid], sdenom[tid]);
}

// ---------------------------------------------------------------------------
// Kernel 3: positives + per-row loss, EXACT fp32 from raw inputs.
// pos_i = sum_m exp(dot(o_i,k_mi)/(|o_i||k_mi|)/T)
// ---------------------------------------------------------------------------
__global__ void pos_loss_kernel(const float* __restrict__ orig,
                                const float* __restrict__ masked,
                                const int* __restrict__ d_iter) {
    const int i = blockIdx.x;
    const int t = threadIdx.x;  // 0..127
    const float4 o = ((const float4*)(orig + (size_t)i * D_))[t];
    float oo = o.x * o.x + o.y * o.y + o.z * o.z + o.w * o.w;
    float dm[M_], km[M_];
    #pragma unroll
    for (int m = 0; m < M_; m++) {
        const float4 kv = ((const float4*)(masked + ((size_t)m * B_ + i) * D_))[t];
        dm[m] = o.x * kv.x + o.y * kv.y + o.z * kv.z + o.w * kv.w;
        km[m] = kv.x * kv.x + kv.y * kv.y + kv.z * kv.z + kv.w * kv.w;
    }
    __shared__ float sm[2 * M_ + 1][4];
    float vals[2 * M_ + 1];
    vals[0] = oo;
    #pragma unroll
    for (int m = 0; m < M_; m++) { vals[1 + m] = dm[m]; vals[1 + M_ + m] = km[m]; }
    #pragma unroll
    for (int q = 0; q < 2 * M_ + 1; q++) {
        float v = vals[q];
        #pragma unroll
        for (int off = 16; off > 0; off >>= 1)
            v += __shfl_down_sync(0xffffffffu, v, off);
        if ((t & 31) == 0) sm[q][t >> 5] = v;
    }
    __syncthreads();
    if (t == 0) {
        const float invT = 1.0f / get_temp(d_iter[0]);
        float tot[2 * M_ + 1];
        #pragma unroll
        for (int q = 0; q < 2 * M_ + 1; q++)
            tot[q] = sm[q][0] + sm[q][1] + sm[q][2] + sm[q][3];
        const float on = fmaxf(sqrtf(tot[0]), 1e-12f);
        float pos = 0.0f;
        #pragma unroll
        for (int m = 0; m < M_; m++) {
            float kn = fmaxf(sqrtf(tot[1 + M_ + m]), 1e-12f);
            pos += __expf(tot[1 + m] / (on * kn) * invT);
        }
        const float denom = g_denom[i];
        const float loss = logf(denom + 1e-8f) - logf(pos);
        atomicAdd(&g_loss_sum, loss);
    }
}

__global__ void finalize_kernel(float* __restrict__ out) {
    out[0] = g_loss_sum * (1.0f / (float)B_);
}

// ---------------------------------------------------------------------------
extern "C" void kernel_launch(void* const* d_in, const int* in_sizes, int n_in,
                              void* d_out, int out_size) {
    const float* orig   = (const float*)d_in[0];
    const float* masked = (const float*)d_in[1];
    const int*   iter   = (const int*)d_in[2];
    float* out = (float*)d_out;

    cudaFuncSetAttribute(gemm_fp8_kernel,
                         cudaFuncAttributeMaxDynamicSharedMemorySize, SMEM_TOTAL);

    normalize_kernel<<<N_, 128>>>(orig, masked);
    gemm_fp8_kernel<<<dim3(N_ / TILE, B_ / TILE), 256, SMEM_TOTAL>>>(iter);
    pos_loss_kernel<<<B_, 128>>>(orig, masked, iter);
    finalize_kernel<<<1, 1>>>(out);
}

// round 7
// speedup vs baseline: 1.2546x; 1.0259x over previous
#include <cuda_runtime.h>
#include <cuda_bf16.h>
#include <math.h>
#include <stdint.h>

#define B_ 4096
#define M_ 4
#define D_ 512
#define N_ ((M_ + 1) * B_)   // 20480

// Static device scratch (no runtime allocation)
__device__ __nv_bfloat16 g_bf16[(size_t)N_ * D_];   // normalized rows, bf16, 20 MB
__device__ float g_denom[B_];
__device__ float g_pos[B_];
__device__ float g_loss_sum;

__device__ __forceinline__ float get_temp(int it) {
    if (it >= 300000) return 0.05f;
    float progress = (float)it / 300000.0f;
    return 0.05f + 0.5f * (0.2f - 0.05f) * (1.0f + cosf(3.14159265358979323846f * progress));
}

__device__ __forceinline__ uint32_t smem_u32(const void* p) {
    uint32_t a;
    asm("{ .reg .u64 t; cvta.to.shared.u64 t, %1; cvt.u32.u64 %0, t; }" : "=r"(a) : "l"(p));
    return a;
}

__device__ __forceinline__ uint32_t swz128(uint32_t off) {
    return off ^ ((off >> 3) & 0x70);
}

#define CP_ASYNC16(dst, src) \
    asm volatile("cp.async.cg.shared.global [%0], [%1], 16;" :: "r"(dst), "l"(src) : "memory")
#define CP_COMMIT() asm volatile("cp.async.commit_group;" ::: "memory")

#define LDMATRIX_X4(r0, r1, r2, r3, addr) \
    asm volatile("ldmatrix.sync.aligned.m8n8.x4.shared.b16 {%0,%1,%2,%3}, [%4];" \
                 : "=r"(r0), "=r"(r1), "=r"(r2), "=r"(r3) : "r"(addr))

#define MMA_BF16(d, a, b0, b1) \
    asm volatile("mma.sync.aligned.m16n8k16.row.col.f32.bf16.bf16.f32 " \
                 "{%0,%1,%2,%3}, {%4,%5,%6,%7}, {%8,%9}, {%0,%1,%2,%3};" \
                 : "+f"((d)[0]), "+f"((d)[1]), "+f"((d)[2]), "+f"((d)[3]) \
                 : "r"((a)[0]), "r"((a)[1]), "r"((a)[2]), "r"((a)[3]), \
                   "r"(b0), "r"(b1))

// ---------------------------------------------------------------------------
// Kernel 1: L2-normalize every row into g_bf16; zero accumulators.
// ---------------------------------------------------------------------------
__global__ void normalize_kernel(const float* __restrict__ orig,
                                 const float* __restrict__ masked) {
    int row = blockIdx.x;
    const float* src = (row < B_) ? (orig + (size_t)row * D_)
                                  : (masked + (size_t)(row - B_) * D_);
    int t = threadIdx.x;  // 0..127
    float4 v = ((const float4*)src)[t];
    float s = v.x * v.x + v.y * v.y + v.z * v.z + v.w * v.w;
    #pragma unroll
    for (int off = 16; off > 0; off >>= 1)
        s += __shfl_down_sync(0xffffffffu, s, off);
    __shared__ float sm[4];
    __shared__ float s_inv;
    if ((t & 31) == 0) sm[t >> 5] = s;
    __syncthreads();
    if (t == 0) {
        float tot = sm[0] + sm[1] + sm[2] + sm[3];
        s_inv = 1.0f / fmaxf(sqrtf(tot), 1e-12f);
        if (row < B_) { g_denom[row] = 0.0f; g_pos[row] = 0.0f; }
        if (row == 0) g_loss_sum = 0.0f;
    }
    __syncthreads();
    float inv = s_inv;
    __nv_bfloat162 lo = __floats2bfloat162_rn(v.x * inv, v.y * inv);
    __nv_bfloat162 hi = __floats2bfloat162_rn(v.z * inv, v.w * inv);
    __nv_bfloat162* dst = (__nv_bfloat162*)(g_bf16 + (size_t)row * D_);
    dst[2 * t]     = lo;
    dst[2 * t + 1] = hi;
}

// ---------------------------------------------------------------------------
// Kernel 2: HMMA exp-GEMM, multi-tile CTAs.
// CTA: 128 rows x 4 column-tiles of 128 (512 cols). 8 warps (64x32 each),
// 256 threads, 2 CTAs/SM. Continuous 3-stage cp.async pipeline across all
// 32 chunks (4 tiles x 8 k-chunks); per-tile exp epilogue overlaps loads.
// ---------------------------------------------------------------------------
#define TILE 128
#define NTILES 4
#define NCH_TOT (NTILES * 8)     // 32
#define NSTAGE 3
#define STG_A_SZ (TILE * 128)    // 16 KB
#define STG_B_SZ (TILE * 128)    // 16 KB
#define SMEM_A_OFF 1024
#define SMEM_B_OFF (SMEM_A_OFF + NSTAGE * STG_A_SZ)
#define SMEM_TOTAL (SMEM_B_OFF + NSTAGE * STG_B_SZ)   // 99328 B

__device__ __forceinline__ void load_chunk(int gc, int stage, uint32_t sb,
                                           const char* gA, const char* gB, int tid) {
    const int kc   = gc & 7;        // k-chunk within tile
    const int tile = gc >> 3;       // column tile index
    const int row = tid >> 1;
    const int c0 = (tid & 1) * 4;
    const char* asrc = gA + (size_t)row * 1024 + kc * 128 + c0 * 16;
    const char* bsrc = gB + (size_t)tile * (TILE * 1024)
                          + (size_t)row * 1024 + kc * 128 + c0 * 16;
    const uint32_t abase = sb + SMEM_A_OFF + stage * STG_A_SZ;
    const uint32_t bbase = sb + SMEM_B_OFF + stage * STG_B_SZ;
    #pragma unroll
    for (int c = 0; c < 4; c++) {
        uint32_t off = (uint32_t)row * 128 + (c0 + c) * 16;
        CP_ASYNC16(abase + swz128(off), asrc + c * 16);
        CP_ASYNC16(bbase + swz128(off), bsrc + c * 16);
    }
}

__global__ __launch_bounds__(256, 2) void gemm_hmma_kernel(const int* __restrict__ d_iter) {
    extern __shared__ __align__(1024) char smem[];
    uint32_t sb = smem_u32(smem);

    const int tid  = threadIdx.x;
    const int wid  = tid >> 5;
    const int lane = tid & 31;
    const int warpM = wid & 1;        // 0/1 -> 64 rows each
    const int warpN = wid >> 1;       // 0..3 -> 32 cols each
    const int rowBase  = blockIdx.y * TILE;
    const int colBase0 = blockIdx.x * (TILE * NTILES);
    const char* gA = (const char*)(g_bf16 + (size_t)rowBase * D_);
    const char* gB = (const char*)(g_bf16 + (size_t)colBase0 * D_);

    load_chunk(0, 0, sb, gA, gB, tid); CP_COMMIT();
    load_chunk(1, 1, sb, gA, gB, tid); CP_COMMIT();

    float acc[4][4][4];
    #pragma unroll
    for (int mt = 0; mt < 4; mt++)
        #pragma unroll
        for (int nt = 0; nt < 4; nt++)
            #pragma unroll
            for (int f = 0; f < 4; f++) acc[mt][nt][f] = 0.0f;

    float RS[4][2];   // persistent per-thread row partial sums (denominator)
    #pragma unroll
    for (int mt = 0; mt < 4; mt++) { RS[mt][0] = 0.0f; RS[mt][1] = 0.0f; }

    const float invT = 1.0f / get_temp(d_iter[0]);

    // per-lane fragment address components
    const int a_row = warpM * 64 + (lane & 15);                       // + mt*16
    const int a_kb  = (lane >> 4) * 16;                               // + kk*32
    const int b_row = warpN * 32 + ((lane >> 4) << 3) + (lane & 7);   // + ntp*16
    const int b_kb  = ((lane >> 3) & 1) * 16;                         // + kk*32

    for (int t = 0; t < NTILES; t++) {
        #pragma unroll
        for (int k = 0; k < 8; k++) {
            const int gc = t * 8 + k;
            if (gc < NCH_TOT - 1) asm volatile("cp.async.wait_group 1;" ::: "memory");
            else                  asm volatile("cp.async.wait_group 0;" ::: "memory");
            __syncthreads();
            if (gc + 2 < NCH_TOT) {
                load_chunk(gc + 2, (gc + 2) % NSTAGE, sb, gA, gB, tid);
                CP_COMMIT();
            }

            const int st = gc % NSTAGE;
            const uint32_t Ab = sb + SMEM_A_OFF + st * STG_A_SZ;
            const uint32_t Bb = sb + SMEM_B_OFF + st * STG_B_SZ;

            #pragma unroll
            for (int kk = 0; kk < 4; kk++) {
                uint32_t a[4][4];
                #pragma unroll
                for (int mt = 0; mt < 4; mt++) {
                    uint32_t off = (uint32_t)(a_row + mt * 16) * 128 + kk * 32 + a_kb;
                    LDMATRIX_X4(a[mt][0], a[mt][1], a[mt][2], a[mt][3], Ab + swz128(off));
                }
                uint32_t b[2][4];
                #pragma unroll
                for (int ntp = 0; ntp < 2; ntp++) {
                    uint32_t off = (uint32_t)(b_row + ntp * 16) * 128 + kk * 32 + b_kb;
                    LDMATRIX_X4(b[ntp][0], b[ntp][1], b[ntp][2], b[ntp][3], Bb + swz128(off));
                }
                #pragma unroll
                for (int mt = 0; mt < 4; mt++)
                    #pragma unroll
                    for (int nt = 0; nt < 4; nt++)
                        MMA_BF16(acc[mt][nt], a[mt], b[nt >> 1][(nt & 1) * 2],
                                 b[nt >> 1][(nt & 1) * 2 + 1]);
            }
        }

        // Per-tile epilogue (overlaps next tile's in-flight cp.async loads):
        // exp, diag mask, accumulate denominator partials, detect positives.
        const int colT = colBase0 + t * TILE;
        #pragma unroll
        for (int mt = 0; mt < 4; mt++) {
            const int r0 = warpM * 64 + mt * 16 + (lane >> 2);
            const int gi0 = rowBase + r0;         // < 4096
            const int gi1 = gi0 + 8;
            float rs0 = 0.0f, rs1 = 0.0f;
            #pragma unroll
            for (int nt = 0; nt < 4; nt++) {
                const int col = colT + warpN * 32 + nt * 8 + 2 * (lane & 3);
                float e0 = __expf(acc[mt][nt][0] * invT);
                float e1 = __expf(acc[mt][nt][1] * invT);
                float e2 = __expf(acc[mt][nt][2] * invT);
                float e3 = __expf(acc[mt][nt][3] * invT);
                if (col != gi0)     rs0 += e0;
                if (col + 1 != gi0) rs0 += e1;
                if (col != gi1)     rs1 += e2;
                if (col + 1 != gi1) rs1 += e3;
                // positives: col == gi + (m+1)*4096  <=>  (col & 4095) == gi, col != gi
                if ((col & 4095) == gi0 && col != gi0)         atomicAdd(&g_pos[gi0], e0);
                if (((col + 1) & 4095) == gi0 && col + 1 != gi0) atomicAdd(&g_pos[gi0], e1);
                if ((col & 4095) == gi1 && col != gi1)         atomicAdd(&g_pos[gi1], e2);
                if (((col + 1) & 4095) == gi1 && col + 1 != gi1) atomicAdd(&g_pos[gi1], e3);
                // zero acc for next tile
                acc[mt][nt][0] = 0.0f; acc[mt][nt][1] = 0.0f;
                acc[mt][nt][2] = 0.0f; acc[mt][nt][3] = 0.0f;
            }
            RS[mt][0] += rs0;
            RS[mt][1] += rs1;
        }
    }

    // Final row reduction: quad shuffle + one global atomic per row-half.
    #pragma unroll
    for (int mt = 0; mt < 4; mt++) {
        const int r0 = warpM * 64 + mt * 16 + (lane >> 2);
        float rs0 = RS[mt][0], rs1 = RS[mt][1];
        rs0 += __shfl_xor_sync(0xffffffffu, rs0, 1);
        rs0 += __shfl_xor_sync(0xffffffffu, rs0, 2);
        rs1 += __shfl_xor_sync(0xffffffffu, rs1, 1);
        rs1 += __shfl_xor_sync(0xffffffffu, rs1, 2);
        if ((lane & 3) == 0) {
            atomicAdd(&g_denom[rowBase + r0], rs0);
            atomicAdd(&g_denom[rowBase + r0 + 8], rs1);
        }
    }
}

// ---------------------------------------------------------------------------
// Kernel 3: per-row loss from g_denom / g_pos, sum via atomics.
// ---------------------------------------------------------------------------
__global__ void loss_kernel() {
    const int i = blockIdx.x * blockDim.x + threadIdx.x;  // < B_
    float loss = logf(g_denom[i] + 1e-8f) - logf(g_pos[i]);
    #pragma unroll
    for (int off = 16; off > 0; off >>= 1)
        loss += __shfl_down_sync(0xffffffffu, loss, off);
    if ((threadIdx.x & 31) == 0) atomicAdd(&g_loss_sum, loss);
}

__global__ void finalize_kernel(float* __restrict__ out) {
    out[0] = g_loss_sum * (1.0f / (float)B_);
}

// ---------------------------------------------------------------------------
extern "C" void kernel_launch(void* const* d_in, const int* in_sizes, int n_in,
                              void* d_out, int out_size) {
    const float* orig   = (const float*)d_in[0];
    const float* masked = (const float*)d_in[1];
    const int*   iter   = (const int*)d_in[2];
    float* out = (float*)d_out;

    cudaFuncSetAttribute(gemm_hmma_kernel,
                         cudaFuncAttributeMaxDynamicSharedMemorySize, SMEM_TOTAL);

    normalize_kernel<<<N_, 128>>>(orig, masked);
    gemm_hmma_kernel<<<dim3(N_ / (TILE * NTILES), B_ / TILE), 256, SMEM_TOTAL>>>(iter);
    loss_kernel<<<B_ / 256, 256>>>();
    finalize_kernel<<<1, 1>>>(out);
}